// round 7
// baseline (speedup 1.0000x reference)
#include <cuda_runtime.h>
#include <stdint.h>

// Problem constants (fixed by the dataset)
#define BATCH   1024
#define IN_DIM  1024
#define OUT_DIM 40960
#define FANIN   7

// Tiling
#define BTILE      32
#define XS_STRIDE  1025           // floats; 1025 % 32 == 1 -> conflict-free gather
#define THREADS    1024
#define WARPS      32
#define GRID_B     (BATCH / BTILE)            // 32
#define GRID_O     80
#define O_BLOCK    (OUT_DIM / GRID_O)         // 512
#define O_PER_WARP (O_BLOCK / WARPS)          // 16 -> one 16-o tile per warp

#define XS_FLOATS    (BTILE * XS_STRIDE)      // 32800
#define META_U4      (O_BLOCK * 3)            // 1536 uint4 = 24576 B
#define META_FLOATS  (META_U4 * 4)            // 6144
#define STG_STRIDE   33                       // 33 % 32 == 1 -> conflict-free
#define STG_PER_WARP (16 * STG_STRIDE)        // 528 floats per warp
#define SMEM_FLOATS  (XS_FLOATS + META_FLOATS + WARPS * STG_PER_WARP)
#define SMEM_BYTES   (SMEM_FLOATS * 4)        // 131200+24576+67584 = 223360 B

// Packed per-output metadata: 48B = uint4 (7x u16 idx*4) + 7 f32 vals + pad
__device__ __align__(16) uint4 g_meta[OUT_DIM * 3];

__global__ void prep_kernel(const int* __restrict__ idx,
                            const float* __restrict__ vals) {
    int o = blockIdx.x * blockDim.x + threadIdx.x;
    if (o >= OUT_DIM) return;
    unsigned id[FANIN];
    float v[FANIN];
#pragma unroll
    for (int k = 0; k < FANIN; k++) {
        id[k] = (unsigned)idx[o * FANIN + k] * 4u;   // pre-scale to byte offset
        v[k]  = vals[o * FANIN + k];
    }
    uint4 mi, ma, mb;
    mi.x = id[0] | (id[1] << 16);
    mi.y = id[2] | (id[3] << 16);
    mi.z = id[4] | (id[5] << 16);
    mi.w = id[6];
    ma.x = __float_as_uint(v[0]); ma.y = __float_as_uint(v[1]);
    ma.z = __float_as_uint(v[2]); ma.w = __float_as_uint(v[3]);
    mb.x = __float_as_uint(v[4]); mb.y = __float_as_uint(v[5]);
    mb.z = __float_as_uint(v[6]); mb.w = 0u;
    uint4* dst = g_meta + (size_t)o * 3;
    dst[0] = mi; dst[1] = ma; dst[2] = mb;
}

// Dot product of 7 gathered x values with 7 vals. xb is this lane's smem row
// base (byte pointer). Gathers are conflict-free: bank = (lane + idx) % 32.
__device__ __forceinline__ float dot7(const char* xb, uint4 mi, uint4 ma, uint4 mb) {
    float g0 = *reinterpret_cast<const float*>(xb + (mi.x & 0xFFFFu));
    float g1 = *reinterpret_cast<const float*>(xb + (mi.x >> 16));
    float g2 = *reinterpret_cast<const float*>(xb + (mi.y & 0xFFFFu));
    float g3 = *reinterpret_cast<const float*>(xb + (mi.y >> 16));
    float g4 = *reinterpret_cast<const float*>(xb + (mi.z & 0xFFFFu));
    float g5 = *reinterpret_cast<const float*>(xb + (mi.z >> 16));
    float g6 = *reinterpret_cast<const float*>(xb + (mi.w & 0xFFFFu));
    float s0 = fmaf(__uint_as_float(ma.x), g0, __uint_as_float(ma.y) * g1);
    float s1 = fmaf(__uint_as_float(ma.z), g2, __uint_as_float(ma.w) * g3);
    float s2 = fmaf(__uint_as_float(mb.x), g4, __uint_as_float(mb.y) * g5);
    float s3 = __uint_as_float(mb.z) * g6;
    return (s0 + s1) + (s2 + s3);
}

extern __shared__ float smem_all[];
// layout: [XS_FLOATS] x-tile | [META_FLOATS] meta | [WARPS][528] store staging

__global__ __launch_bounds__(THREADS, 1)
void mb_proj_kernel(const float* __restrict__ x, float* __restrict__ y) {
    float* xs = smem_all;
    uint4* meta_s = reinterpret_cast<uint4*>(smem_all + XS_FLOATS);
    const int b0     = blockIdx.y * BTILE;
    const int o_cta  = blockIdx.x * O_BLOCK;

    // ---- Async meta load: 512 o x 48B = 1536 x 16B, coalesced ------------
    {
        const char* gsrc = reinterpret_cast<const char*>(g_meta + (size_t)o_cta * 3);
        unsigned sbase = (unsigned)__cvta_generic_to_shared(meta_s);
        for (int i = threadIdx.x; i < META_U4; i += THREADS) {
            unsigned sdst = sbase + i * 16;
            asm volatile("cp.async.cg.shared.global [%0], [%1], 16;\n"
                         :: "r"(sdst), "l"(gsrc + (size_t)i * 16));
        }
        asm volatile("cp.async.commit_group;\n");
    }

    // ---- Fill smem x tile: 32 rows x 1024 floats, stride 1025 -------------
    // Warp mapping: 4 rows x 8 float4-chunks -> coalesced LDG segments,
    // STS banks = (r + 4c + j) mod 32 cover all 32 -> conflict-free stores.
    {
        const float4* xg = reinterpret_cast<const float4*>(x + (size_t)b0 * IN_DIM);
        for (int t = threadIdx.x; t < BTILE * (IN_DIM / 4); t += THREADS) {
            int lane5 = t & 31;
            int blk   = t >> 5;
            int r = ((blk >> 5) << 2) + (lane5 >> 3);   // 0..31
            int c = ((blk & 31) << 3) + (lane5 & 7);    // 0..255 (float4 units)
            float4 v = xg[r * (IN_DIM / 4) + c];
            float* d = xs + r * XS_STRIDE + (c << 2);
            d[0] = v.x; d[1] = v.y; d[2] = v.z; d[3] = v.w;
        }
    }
    asm volatile("cp.async.wait_group 0;\n");
    __syncthreads();

    const int warp = threadIdx.x >> 5;
    const int lane = threadIdx.x & 31;

    // Compute mapping: lane = batch row, o uniform across warp.
    const char* xb = reinterpret_cast<const char*>(xs) + lane * (XS_STRIDE * 4);
    float* stg = smem_all + XS_FLOATS + META_FLOATS + warp * STG_PER_WARP;

    const int o0 = o_cta + warp * O_PER_WARP;           // global o base
    const uint4* mp = meta_s + warp * (O_PER_WARP * 3); // smem meta base

    // ---- Compute 16 outputs into staging; meta via broadcast LDS ---------
    {
        uint4 c0 = mp[0], c1 = mp[1], c2 = mp[2];
#pragma unroll
        for (int s = 0; s < 16; s++) {
            uint4 n0, n1, n2;
            if (s < 15) {
                const uint4* np = mp + 3 * (s + 1);
                n0 = np[0]; n1 = np[1]; n2 = np[2];
            } else {
                n0 = c0; n1 = c1; n2 = c2;
            }
            // STS bank = (s + lane) % 32 -> conflict-free
            stg[s * STG_STRIDE + lane] = dot7(xb, c0, c1, c2);
            c0 = n0; c1 = n1; c2 = n2;
        }
    }
    __syncwarp();

    // ---- Transposed store: coalesced y rows ------------------------------
    // lane = (hh, t): o = o0 + t, b = i + 16*hh.
    // LDS addr = t*33 + 16*hh + i -> bank = (t + 16*hh + i) % 32, all 32
    // distinct -> conflict-free. STG: 2 row-segments of 64B per iter.
    {
        const int t  = lane & 15;
        const int hh = lane >> 4;
        const float* sp = stg + t * STG_STRIDE + 16 * hh;
        float* yp = y + (size_t)(b0 + 16 * hh) * OUT_DIM + o0 + t;
#pragma unroll
        for (int i = 0; i < 16; i++) {
            yp[(size_t)i * OUT_DIM] = sp[i];
        }
    }
}

extern "C" void kernel_launch(void* const* d_in, const int* in_sizes, int n_in,
                              void* d_out, int out_size) {
    const float* x    = (const float*)d_in[0];   // [1024, 1024] f32
    const float* vals = (const float*)d_in[1];   // [40960, 7]   f32
    const int*   idx  = (const int*)d_in[2];     // [40960, 7]   i32
    float*       y    = (float*)d_out;           // [1024, 40960] f32

    (void)in_sizes; (void)n_in; (void)out_size;

    cudaFuncSetAttribute(mb_proj_kernel,
                         cudaFuncAttributeMaxDynamicSharedMemorySize, SMEM_BYTES);

    prep_kernel<<<(OUT_DIM + 255) / 256, 256>>>(idx, vals);

    dim3 grid(GRID_O, GRID_B);
    mb_proj_kernel<<<grid, THREADS, SMEM_BYTES>>>(x, y);
}

// round 8
// speedup vs baseline: 1.2716x; 1.2716x over previous
#include <cuda_runtime.h>
#include <stdint.h>

// Problem constants (fixed by the dataset)
#define BATCH   1024
#define IN_DIM  1024
#define OUT_DIM 40960
#define FANIN   7

// Tiling
#define BTILE      32
#define XS_STRIDE  1025           // floats; 1025 % 32 == 1 -> conflict-free gather
#define THREADS    1024
#define WARPS      32
#define GRID_B     (BATCH / BTILE)            // 32
#define GRID_O     40
#define O_BLOCK    (OUT_DIM / GRID_O)         // 1024
#define CHUNK_O    512                        // per meta-buffer chunk
#define O_PER_WARP 16                         // one 16-o tile per warp per chunk

#define XS_FLOATS    (BTILE * XS_STRIDE)      // 32800
#define META_U4      (CHUNK_O * 3)            // 1536 uint4 = 24576 B
#define META_FLOATS  (META_U4 * 4)            // 6144
#define STG_STRIDE   33                       // 33 % 32 == 1 -> conflict-free
#define STG_PER_WARP (16 * STG_STRIDE)        // 528 floats per warp
#define SMEM_FLOATS  (XS_FLOATS + META_FLOATS + WARPS * STG_PER_WARP)
#define SMEM_BYTES   (SMEM_FLOATS * 4)        // 131200+24576+67584 = 223360 B

// Packed per-output metadata: 48B = uint4 (7x u16 idx*4) + 7 f32 vals + pad
__device__ __align__(16) uint4 g_meta[OUT_DIM * 3];

__global__ void prep_kernel(const int* __restrict__ idx,
                            const float* __restrict__ vals) {
    int o = blockIdx.x * blockDim.x + threadIdx.x;
    if (o >= OUT_DIM) return;
    unsigned id[FANIN];
    float v[FANIN];
#pragma unroll
    for (int k = 0; k < FANIN; k++) {
        id[k] = (unsigned)idx[o * FANIN + k] * 4u;   // pre-scale to byte offset
        v[k]  = vals[o * FANIN + k];
    }
    uint4 mi, ma, mb;
    mi.x = id[0] | (id[1] << 16);
    mi.y = id[2] | (id[3] << 16);
    mi.z = id[4] | (id[5] << 16);
    mi.w = id[6];
    ma.x = __float_as_uint(v[0]); ma.y = __float_as_uint(v[1]);
    ma.z = __float_as_uint(v[2]); ma.w = __float_as_uint(v[3]);
    mb.x = __float_as_uint(v[4]); mb.y = __float_as_uint(v[5]);
    mb.z = __float_as_uint(v[6]); mb.w = 0u;
    uint4* dst = g_meta + (size_t)o * 3;
    dst[0] = mi; dst[1] = ma; dst[2] = mb;
}

// Dot product of 7 gathered x values with 7 vals. xb is this lane's smem row
// base (byte pointer). Gathers are conflict-free: bank = (lane + idx) % 32.
__device__ __forceinline__ float dot7(const char* xb, uint4 mi, uint4 ma, uint4 mb) {
    float g0 = *reinterpret_cast<const float*>(xb + (mi.x & 0xFFFFu));
    float g1 = *reinterpret_cast<const float*>(xb + (mi.x >> 16));
    float g2 = *reinterpret_cast<const float*>(xb + (mi.y & 0xFFFFu));
    float g3 = *reinterpret_cast<const float*>(xb + (mi.y >> 16));
    float g4 = *reinterpret_cast<const float*>(xb + (mi.z & 0xFFFFu));
    float g5 = *reinterpret_cast<const float*>(xb + (mi.z >> 16));
    float g6 = *reinterpret_cast<const float*>(xb + (mi.w & 0xFFFFu));
    float s0 = fmaf(__uint_as_float(ma.x), g0, __uint_as_float(ma.y) * g1);
    float s1 = fmaf(__uint_as_float(ma.z), g2, __uint_as_float(ma.w) * g3);
    float s2 = fmaf(__uint_as_float(mb.x), g4, __uint_as_float(mb.y) * g5);
    float s3 = __uint_as_float(mb.z) * g6;
    return (s0 + s1) + (s2 + s3);
}

__device__ __forceinline__ void load_meta_chunk(uint4* meta_s, int o_chunk) {
    const char* gsrc = reinterpret_cast<const char*>(g_meta + (size_t)o_chunk * 3);
    unsigned sbase = (unsigned)__cvta_generic_to_shared(meta_s);
    for (int i = threadIdx.x; i < META_U4; i += THREADS) {
        unsigned sdst = sbase + i * 16;
        asm volatile("cp.async.cg.shared.global [%0], [%1], 16;\n"
                     :: "r"(sdst), "l"(gsrc + (size_t)i * 16));
    }
    asm volatile("cp.async.commit_group;\n");
}

extern __shared__ float smem_all[];
// layout: [XS_FLOATS] x-tile | [META_FLOATS] meta chunk | [WARPS][528] staging

__global__ __launch_bounds__(THREADS, 1)
void mb_proj_kernel(const float* __restrict__ x, float* __restrict__ y) {
    float* xs = smem_all;
    uint4* meta_s = reinterpret_cast<uint4*>(smem_all + XS_FLOATS);
    const int b0    = blockIdx.y * BTILE;
    const int o_cta = blockIdx.x * O_BLOCK;

    // ---- Async meta load for chunk 0, overlapped with x-tile fill --------
    load_meta_chunk(meta_s, o_cta);

    // ---- Fill smem x tile: 32 rows x 1024 floats, stride 1025 -------------
    // Warp mapping: 4 rows x 8 float4-chunks -> coalesced LDG segments,
    // STS banks = (r + 4c + j) mod 32 cover all 32 -> conflict-free stores.
    {
        const float4* xg = reinterpret_cast<const float4*>(x + (size_t)b0 * IN_DIM);
        for (int t = threadIdx.x; t < BTILE * (IN_DIM / 4); t += THREADS) {
            int lane5 = t & 31;
            int blk   = t >> 5;
            int r = ((blk >> 5) << 2) + (lane5 >> 3);   // 0..31
            int c = ((blk & 31) << 3) + (lane5 & 7);    // 0..255 (float4 units)
            float4 v = xg[r * (IN_DIM / 4) + c];
            float* d = xs + r * XS_STRIDE + (c << 2);
            d[0] = v.x; d[1] = v.y; d[2] = v.z; d[3] = v.w;
        }
    }
    asm volatile("cp.async.wait_group 0;\n");
    __syncthreads();

    const int warp = threadIdx.x >> 5;
    const int lane = threadIdx.x & 31;

    // Compute mapping: lane = batch row, o uniform across warp.
    const char* xb = reinterpret_cast<const char*>(xs) + lane * (XS_STRIDE * 4);
    float* stg = smem_all + XS_FLOATS + META_FLOATS + warp * STG_PER_WARP;

    // Store-phase mapping: lane = (hh, t): o = o0 + t, b = i + 16*hh.
    const int t  = lane & 15;
    const int hh = lane >> 4;

#pragma unroll
    for (int chunk = 0; chunk < 2; chunk++) {
        const int o0 = o_cta + chunk * CHUNK_O + warp * O_PER_WARP;
        const uint4* mp = meta_s + warp * (O_PER_WARP * 3);

        // ---- Compute 16 outputs into staging; meta via broadcast LDS ----
        {
            uint4 c0 = mp[0], c1 = mp[1], c2 = mp[2];
#pragma unroll
            for (int s = 0; s < 16; s++) {
                uint4 n0, n1, n2;
                if (s < 15) {
                    const uint4* np = mp + 3 * (s + 1);
                    n0 = np[0]; n1 = np[1]; n2 = np[2];
                } else {
                    n0 = c0; n1 = c1; n2 = c2;
                }
                // STS bank = (s + lane) % 32 -> conflict-free
                stg[s * STG_STRIDE + lane] = dot7(xb, c0, c1, c2);
                c0 = n0; c1 = n1; c2 = n2;
            }
        }
        __syncwarp();

        // ---- Transposed store: coalesced y rows -------------------------
        // LDS addr = t*33 + 16*hh + i -> bank = (t + 16*hh + i) % 32, all
        // 32 distinct -> conflict-free. STG: 2 row-segments of 64B per iter.
        {
            const float* sp = stg + t * STG_STRIDE + 16 * hh;
            float* yp = y + (size_t)(b0 + 16 * hh) * OUT_DIM + o0 + t;
#pragma unroll
            for (int i = 0; i < 16; i++) {
                yp[(size_t)i * OUT_DIM] = sp[i];
            }
        }

        // ---- Reload meta buffer for chunk 1 -----------------------------
        if (chunk == 0) {
            __syncthreads();            // all warps done reading meta buf
            load_meta_chunk(meta_s, o_cta + CHUNK_O);
            asm volatile("cp.async.wait_group 0;\n");
            __syncthreads();            // meta chunk 1 visible to all
        }
    }
}

extern "C" void kernel_launch(void* const* d_in, const int* in_sizes, int n_in,
                              void* d_out, int out_size) {
    const float* x    = (const float*)d_in[0];   // [1024, 1024] f32
    const float* vals = (const float*)d_in[1];   // [40960, 7]   f32
    const int*   idx  = (const int*)d_in[2];     // [40960, 7]   i32
    float*       y    = (float*)d_out;           // [1024, 40960] f32

    (void)in_sizes; (void)n_in; (void)out_size;

    cudaFuncSetAttribute(mb_proj_kernel,
                         cudaFuncAttributeMaxDynamicSharedMemorySize, SMEM_BYTES);

    prep_kernel<<<(OUT_DIM + 255) / 256, 256>>>(idx, vals);

    dim3 grid(GRID_O, GRID_B);
    mb_proj_kernel<<<grid, THREADS, SMEM_BYTES>>>(x, y);
}

// round 9
// speedup vs baseline: 1.4904x; 1.1721x over previous
#include <cuda_runtime.h>
#include <stdint.h>

// Problem constants (fixed by the dataset)
#define BATCH   1024
#define IN_DIM  1024
#define OUT_DIM 40960
#define FANIN   7

// Tiling
#define BTILE      32
#define XS_STRIDE  1025           // floats; 1025 % 32 == 1 -> conflict-free gather
#define THREADS    1024
#define WARPS      32
#define GRID_B     (BATCH / BTILE)            // 32
#define GRID_O     40
#define O_BLOCK    (OUT_DIM / GRID_O)         // 1024
#define CHUNK_O    512                        // per meta-buffer chunk
#define O_PER_WARP 16                         // one 16-o tile per warp per chunk

#define XS_FLOATS    (BTILE * XS_STRIDE)      // 32800
#define META_U4      (CHUNK_O * 3)            // 1536 uint4 = 24576 B
#define META_FLOATS  (META_U4 * 4)            // 6144
#define STG_STRIDE   33                       // 33 % 32 == 1 -> conflict-free
#define STG_PER_WARP (16 * STG_STRIDE)        // 528 floats per warp
#define SMEM_FLOATS  (XS_FLOATS + META_FLOATS + WARPS * STG_PER_WARP)
#define SMEM_BYTES   (SMEM_FLOATS * 4)        // 131200+24576+67584 = 223360 B

#define FILL_ITERS   (BTILE * (IN_DIM / 4) / THREADS)   // 8

// Packed per-output metadata: 48B = uint4 (7x u16 idx*4) + 7 f32 vals + pad
__device__ __align__(16) uint4 g_meta[OUT_DIM * 3];

__global__ void prep_kernel(const int* __restrict__ idx,
                            const float* __restrict__ vals) {
    int o = blockIdx.x * blockDim.x + threadIdx.x;
    if (o >= OUT_DIM) return;
    unsigned id[FANIN];
    float v[FANIN];
#pragma unroll
    for (int k = 0; k < FANIN; k++) {
        id[k] = (unsigned)idx[o * FANIN + k] * 4u;   // pre-scale to byte offset
        v[k]  = vals[o * FANIN + k];
    }
    uint4 mi, ma, mb;
    mi.x = id[0] | (id[1] << 16);
    mi.y = id[2] | (id[3] << 16);
    mi.z = id[4] | (id[5] << 16);
    mi.w = id[6];
    ma.x = __float_as_uint(v[0]); ma.y = __float_as_uint(v[1]);
    ma.z = __float_as_uint(v[2]); ma.w = __float_as_uint(v[3]);
    mb.x = __float_as_uint(v[4]); mb.y = __float_as_uint(v[5]);
    mb.z = __float_as_uint(v[6]); mb.w = 0u;
    uint4* dst = g_meta + (size_t)o * 3;
    dst[0] = mi; dst[1] = ma; dst[2] = mb;
}

// Dot product of 7 gathered x values with 7 vals. xb is this lane's smem row
// base (byte pointer). Gathers are conflict-free: bank = (lane + idx) % 32.
__device__ __forceinline__ float dot7(const char* xb, uint4 mi, uint4 ma, uint4 mb) {
    float g0 = *reinterpret_cast<const float*>(xb + (mi.x & 0xFFFFu));
    float g1 = *reinterpret_cast<const float*>(xb + (mi.x >> 16));
    float g2 = *reinterpret_cast<const float*>(xb + (mi.y & 0xFFFFu));
    float g3 = *reinterpret_cast<const float*>(xb + (mi.y >> 16));
    float g4 = *reinterpret_cast<const float*>(xb + (mi.z & 0xFFFFu));
    float g5 = *reinterpret_cast<const float*>(xb + (mi.z >> 16));
    float g6 = *reinterpret_cast<const float*>(xb + (mi.w & 0xFFFFu));
    float s0 = fmaf(__uint_as_float(ma.x), g0, __uint_as_float(ma.y) * g1);
    float s1 = fmaf(__uint_as_float(ma.z), g2, __uint_as_float(ma.w) * g3);
    float s2 = fmaf(__uint_as_float(mb.x), g4, __uint_as_float(mb.y) * g5);
    float s3 = __uint_as_float(mb.z) * g6;
    return (s0 + s1) + (s2 + s3);
}

__device__ __forceinline__ void load_meta_chunk(uint4* meta_s, int o_chunk) {
    const char* gsrc = reinterpret_cast<const char*>(g_meta + (size_t)o_chunk * 3);
    unsigned sbase = (unsigned)__cvta_generic_to_shared(meta_s);
    for (int i = threadIdx.x; i < META_U4; i += THREADS) {
        unsigned sdst = sbase + i * 16;
        asm volatile("cp.async.cg.shared.global [%0], [%1], 16;\n"
                     :: "r"(sdst), "l"(gsrc + (size_t)i * 16));
    }
    asm volatile("cp.async.commit_group;\n");
}

extern __shared__ float smem_all[];
// layout: [XS_FLOATS] x-tile | [META_FLOATS] meta chunk | [WARPS][528] staging

__global__ __launch_bounds__(THREADS, 1)
void mb_proj_kernel(const float* __restrict__ x, float* __restrict__ y) {
    float* xs = smem_all;
    uint4* meta_s = reinterpret_cast<uint4*>(smem_all + XS_FLOATS);
    const int b0    = blockIdx.y * BTILE;
    const int o_cta = blockIdx.x * O_BLOCK;

    // ---- Async meta load for chunk 0, overlapped with x-tile fill --------
    load_meta_chunk(meta_s, o_cta);

    // ---- Fill smem x tile: 32 rows x 1024 floats, stride 1025 -------------
    // All 8 LDG.128 issued back-to-back into registers (MLP=8), then 8 STS.
    // Warp mapping: 4 rows x 8 float4-chunks -> coalesced LDG segments,
    // STS banks = (r + 4c + j) mod 32 cover all 32 -> conflict-free stores.
    {
        const float4* xg = reinterpret_cast<const float4*>(x + (size_t)b0 * IN_DIM);
        float4 v[FILL_ITERS];
#pragma unroll
        for (int i = 0; i < FILL_ITERS; i++) {
            int t = threadIdx.x + i * THREADS;
            int lane5 = t & 31;
            int blk   = t >> 5;
            int r = ((blk >> 5) << 2) + (lane5 >> 3);   // 0..31
            int c = ((blk & 31) << 3) + (lane5 & 7);    // 0..255 (float4 units)
            v[i] = xg[r * (IN_DIM / 4) + c];
        }
#pragma unroll
        for (int i = 0; i < FILL_ITERS; i++) {
            int t = threadIdx.x + i * THREADS;
            int lane5 = t & 31;
            int blk   = t >> 5;
            int r = ((blk >> 5) << 2) + (lane5 >> 3);
            int c = ((blk & 31) << 3) + (lane5 & 7);
            float* d = xs + r * XS_STRIDE + (c << 2);
            d[0] = v[i].x; d[1] = v[i].y; d[2] = v[i].z; d[3] = v[i].w;
        }
    }
    asm volatile("cp.async.wait_group 0;\n");
    __syncthreads();

    const int warp = threadIdx.x >> 5;
    const int lane = threadIdx.x & 31;

    // Compute mapping: lane = batch row, o uniform across warp.
    const char* xb = reinterpret_cast<const char*>(xs) + lane * (XS_STRIDE * 4);
    float* stg = smem_all + XS_FLOATS + META_FLOATS + warp * STG_PER_WARP;

    // Store-phase mapping: lane = (hh, t): o = o0 + t, b = i + 16*hh.
    const int t  = lane & 15;
    const int hh = lane >> 4;

#pragma unroll
    for (int chunk = 0; chunk < 2; chunk++) {
        const int o0 = o_cta + chunk * CHUNK_O + warp * O_PER_WARP;
        const uint4* mp = meta_s + warp * (O_PER_WARP * 3);

        // ---- Compute 16 outputs into staging; meta via broadcast LDS ----
        // Explicit next-meta rotation keeps the LDS pipeline ahead of the
        // staging STS (ptxas must assume smem aliasing otherwise).
        {
            uint4 c0 = mp[0], c1 = mp[1], c2 = mp[2];
#pragma unroll
            for (int s = 0; s < 16; s++) {
                uint4 n0, n1, n2;
                if (s < 15) {
                    const uint4* np = mp + 3 * (s + 1);
                    n0 = np[0]; n1 = np[1]; n2 = np[2];
                } else {
                    n0 = c0; n1 = c1; n2 = c2;
                }
                // STS bank = (s + lane) % 32 -> conflict-free
                stg[s * STG_STRIDE + lane] = dot7(xb, c0, c1, c2);
                c0 = n0; c1 = n1; c2 = n2;
            }
        }

        if (chunk == 0) {
            // All warps finished reading meta chunk 0 -> start async load of
            // chunk 1 NOW; its L2 latency hides under the store phase below.
            __syncthreads();
            load_meta_chunk(meta_s, o_cta + CHUNK_O);
        } else {
            __syncwarp();
        }

        // ---- Transposed store: coalesced y rows -------------------------
        // LDS addr = t*33 + 16*hh + i -> bank = (t + 16*hh + i) % 32, all
        // 32 distinct -> conflict-free. STG: 2 row-segments of 64B per iter.
        {
            const float* sp = stg + t * STG_STRIDE + 16 * hh;
            float* yp = y + (size_t)(b0 + 16 * hh) * OUT_DIM + o0 + t;
#pragma unroll
            for (int i = 0; i < 16; i++) {
                yp[(size_t)i * OUT_DIM] = sp[i];
            }
        }

        if (chunk == 0) {
            asm volatile("cp.async.wait_group 0;\n");
            __syncthreads();            // meta chunk 1 visible to all
        }
    }
}

extern "C" void kernel_launch(void* const* d_in, const int* in_sizes, int n_in,
                              void* d_out, int out_size) {
    const float* x    = (const float*)d_in[0];   // [1024, 1024] f32
    const float* vals = (const float*)d_in[1];   // [40960, 7]   f32
    const int*   idx  = (const int*)d_in[2];     // [40960, 7]   i32
    float*       y    = (float*)d_out;           // [1024, 40960] f32

    (void)in_sizes; (void)n_in; (void)out_size;

    cudaFuncSetAttribute(mb_proj_kernel,
                         cudaFuncAttributeMaxDynamicSharedMemorySize, SMEM_BYTES);

    prep_kernel<<<(OUT_DIM + 255) / 256, 256>>>(idx, vals);

    dim3 grid(GRID_O, GRID_B);
    mb_proj_kernel<<<grid, THREADS, SMEM_BYTES>>>(x, y);
}

// round 11
// speedup vs baseline: 1.4949x; 1.0030x over previous
#include <cuda_runtime.h>
#include <stdint.h>

// Problem constants (fixed by the dataset)
#define BATCH   1024
#define IN_DIM  1024
#define OUT_DIM 40960
#define FANIN   7

// Tiling
#define BTILE      32
#define XS_STRIDE  1025           // floats; 1025 % 32 == 1 -> conflict-free gather
#define THREADS    1024
#define WARPS      32
#define GRID_B     (BATCH / BTILE)            // 32
#define GRID_O     40
#define O_BLOCK    (OUT_DIM / GRID_O)         // 1024
#define CHUNK_O    512                        // per meta-buffer chunk
#define O_PER_WARP 16                         // one 16-o tile per warp per chunk

#define XS_FLOATS    (BTILE * XS_STRIDE)      // 32800
#define META_U4      (CHUNK_O * 3)            // 1536 uint4 = 24576 B
#define META_FLOATS  (META_U4 * 4)            // 6144
#define PAIR_STG_FLOATS (32 * 33)             // 1056 floats per warp PAIR
#define NPAIRS       (WARPS / 2)              // 16
#define SMEM_FLOATS  (XS_FLOATS + META_FLOATS + NPAIRS * PAIR_STG_FLOATS)
#define SMEM_BYTES   (SMEM_FLOATS * 4)        // 131200+24576+67584 = 223360 B

#define FILL_ITERS   (BTILE * (IN_DIM / 4) / THREADS)   // 8

// Packed per-output metadata: 48B = uint4 (7x u16 idx*4) + 7 f32 vals + pad
__device__ __align__(16) uint4 g_meta[OUT_DIM * 3];

__global__ void prep_kernel(const int* __restrict__ idx,
                            const float* __restrict__ vals) {
    int o = blockIdx.x * blockDim.x + threadIdx.x;
    if (o >= OUT_DIM) return;
    unsigned id[FANIN];
    float v[FANIN];
#pragma unroll
    for (int k = 0; k < FANIN; k++) {
        id[k] = (unsigned)idx[o * FANIN + k] * 4u;   // pre-scale to byte offset
        v[k]  = vals[o * FANIN + k];
    }
    uint4 mi, ma, mb;
    mi.x = id[0] | (id[1] << 16);
    mi.y = id[2] | (id[3] << 16);
    mi.z = id[4] | (id[5] << 16);
    mi.w = id[6];
    ma.x = __float_as_uint(v[0]); ma.y = __float_as_uint(v[1]);
    ma.z = __float_as_uint(v[2]); ma.w = __float_as_uint(v[3]);
    mb.x = __float_as_uint(v[4]); mb.y = __float_as_uint(v[5]);
    mb.z = __float_as_uint(v[6]); mb.w = 0u;
    uint4* dst = g_meta + (size_t)o * 3;
    dst[0] = mi; dst[1] = ma; dst[2] = mb;
}

// Dot product of 7 gathered x values with 7 vals. xb is this lane's smem row
// base (byte pointer). Gathers are conflict-free: bank = (lane + idx) % 32.
__device__ __forceinline__ float dot7(const char* xb, uint4 mi, uint4 ma, uint4 mb) {
    float g0 = *reinterpret_cast<const float*>(xb + (mi.x & 0xFFFFu));
    float g1 = *reinterpret_cast<const float*>(xb + (mi.x >> 16));
    float g2 = *reinterpret_cast<const float*>(xb + (mi.y & 0xFFFFu));
    float g3 = *reinterpret_cast<const float*>(xb + (mi.y >> 16));
    float g4 = *reinterpret_cast<const float*>(xb + (mi.z & 0xFFFFu));
    float g5 = *reinterpret_cast<const float*>(xb + (mi.z >> 16));
    float g6 = *reinterpret_cast<const float*>(xb + (mi.w & 0xFFFFu));
    float s0 = fmaf(__uint_as_float(ma.x), g0, __uint_as_float(ma.y) * g1);
    float s1 = fmaf(__uint_as_float(ma.z), g2, __uint_as_float(ma.w) * g3);
    float s2 = fmaf(__uint_as_float(mb.x), g4, __uint_as_float(mb.y) * g5);
    float s3 = __uint_as_float(mb.z) * g6;
    return (s0 + s1) + (s2 + s3);
}

__device__ __forceinline__ void load_meta_chunk(uint4* meta_s, int o_chunk) {
    // 16B records into a 16B-aligned contiguous buffer: cp.async-safe.
    const char* gsrc = reinterpret_cast<const char*>(g_meta + (size_t)o_chunk * 3);
    unsigned sbase = (unsigned)__cvta_generic_to_shared(meta_s);
    for (int i = threadIdx.x; i < META_U4; i += THREADS) {
        unsigned sdst = sbase + i * 16;
        asm volatile("cp.async.cg.shared.global [%0], [%1], 16;\n"
                     :: "r"(sdst), "l"(gsrc + (size_t)i * 16));
    }
    asm volatile("cp.async.commit_group;\n");
}

extern __shared__ float smem_all[];
// layout: [XS_FLOATS] x-tile | [META_FLOATS] meta chunk | [NPAIRS][1056] staging

__global__ __launch_bounds__(THREADS, 1)
void mb_proj_kernel(const float* __restrict__ x, float* __restrict__ y) {
    float* xs = smem_all;
    uint4* meta_s = reinterpret_cast<uint4*>(smem_all + XS_FLOATS);
    const int b0    = blockIdx.y * BTILE;
    const int o_cta = blockIdx.x * O_BLOCK;

    // ---- Async meta load for chunk 0 (overlaps x-tile fill) --------------
    load_meta_chunk(meta_s, o_cta);

    // ---- Fill smem x tile: 32 rows x 1024 floats, stride 1025 -------------
    // NOTE: row stride 4100B is only 4B-aligned -> cp.async.16 is ILLEGAL
    // here (caused R9's misaligned-address fault). Use batched LDG.128 into
    // registers (MLP=8) + scalar STS, proven in R8.
    // Warp mapping: 4 rows x 8 float4-chunks -> coalesced LDG segments,
    // STS banks = (r + 4c + j) mod 32 cover all 32 -> conflict-free stores.
    {
        const float4* xg = reinterpret_cast<const float4*>(x + (size_t)b0 * IN_DIM);
        float4 v[FILL_ITERS];
#pragma unroll
        for (int i = 0; i < FILL_ITERS; i++) {
            int t = threadIdx.x + i * THREADS;
            int lane5 = t & 31;
            int blk   = t >> 5;
            int r = ((blk >> 5) << 2) + (lane5 >> 3);   // 0..31
            int c = ((blk & 31) << 3) + (lane5 & 7);    // 0..255 (float4 units)
            v[i] = xg[r * (IN_DIM / 4) + c];
        }
#pragma unroll
        for (int i = 0; i < FILL_ITERS; i++) {
            int t = threadIdx.x + i * THREADS;
            int lane5 = t & 31;
            int blk   = t >> 5;
            int r = ((blk >> 5) << 2) + (lane5 >> 3);
            int c = ((blk & 31) << 3) + (lane5 & 7);
            float* d = xs + r * XS_STRIDE + (c << 2);
            d[0] = v[i].x; d[1] = v[i].y; d[2] = v[i].z; d[3] = v[i].w;
        }
    }
    asm volatile("cp.async.wait_group 0;\n");
    __syncthreads();

    const int warp = threadIdx.x >> 5;
    const int lane = threadIdx.x & 31;
    const int pair = warp >> 1;
    const int w2   = warp & 1;

    // Compute mapping: lane = batch row, o uniform across warp.
    const char* xb = reinterpret_cast<const char*>(xs) + lane * (XS_STRIDE * 4);
    // Warp-PAIR staging: 32 o x 32 b (stride 33, conflict-free both phases)
    float* stgp  = smem_all + XS_FLOATS + META_FLOATS + pair * PAIR_STG_FLOATS;
    float* stg_w = stgp + w2 * (16 * 33);   // this warp's 16-o half

#pragma unroll
    for (int chunk = 0; chunk < 2; chunk++) {
        const uint4* mp = meta_s + warp * (O_PER_WARP * 3);

        // ---- Compute 16 outputs into pair staging; meta via bcast LDS ----
        // Explicit next-meta rotation keeps the LDS pipeline ahead of the
        // staging STS (ptxas must assume smem aliasing otherwise).
        {
            uint4 c0 = mp[0], c1 = mp[1], c2 = mp[2];
#pragma unroll
            for (int s = 0; s < 16; s++) {
                uint4 n0, n1, n2;
                if (s < 15) {
                    const uint4* np = mp + 3 * (s + 1);
                    n0 = np[0]; n1 = np[1]; n2 = np[2];
                } else {
                    n0 = c0; n1 = c1; n2 = c2;
                }
                // STS bank = (s + lane) % 32 -> conflict-free
                stg_w[s * 33 + lane] = dot7(xb, c0, c1, c2);
                c0 = n0; c1 = n1; c2 = n2;
            }
        }

        // Pair exchange barrier; chunk 0 also kicks off meta chunk 1 whose
        // L2 latency hides under the store phase below.
        __syncthreads();
        if (chunk == 0) {
            load_meta_chunk(meta_s, o_cta + CHUNK_O);
        }

        // ---- Store pair tile: 32 o x 32 b, coalesced 128B rows ----------
        // lane = o. LDS bank = (lane*33 + b) % 32 = (lane + b) % 32, all 32
        // distinct -> conflict-free. Each STG covers one contiguous 128B
        // row segment -> 1 wavefront per instruction (was 2 with 16-o tiles).
        {
            const int o_pair = o_cta + chunk * CHUNK_O + pair * 32;
            float* yp = y + (size_t)(b0 + 16 * w2) * OUT_DIM + o_pair + lane;
#pragma unroll
            for (int i = 0; i < 16; i++) {
                yp[(size_t)i * OUT_DIM] = stgp[lane * 33 + 16 * w2 + i];
            }
        }

        if (chunk == 0) {
            asm volatile("cp.async.wait_group 0;\n");
            __syncthreads();   // meta chunk 1 visible; staging reads done
        }
    }
}

extern "C" void kernel_launch(void* const* d_in, const int* in_sizes, int n_in,
                              void* d_out, int out_size) {
    const float* x    = (const float*)d_in[0];   // [1024, 1024] f32
    const float* vals = (const float*)d_in[1];   // [40960, 7]   f32
    const int*   idx  = (const int*)d_in[2];     // [40960, 7]   i32
    float*       y    = (float*)d_out;           // [1024, 40960] f32

    (void)in_sizes; (void)n_in; (void)out_size;

    cudaFuncSetAttribute(mb_proj_kernel,
                         cudaFuncAttributeMaxDynamicSharedMemorySize, SMEM_BYTES);

    prep_kernel<<<(OUT_DIM + 255) / 256, 256>>>(idx, vals);

    dim3 grid(GRID_O, GRID_B);
    mb_proj_kernel<<<grid, THREADS, SMEM_BYTES>>>(x, y);
}

// round 12
// speedup vs baseline: 1.5630x; 1.0456x over previous
#include <cuda_runtime.h>
#include <stdint.h>

// Problem constants (fixed by the dataset)
#define BATCH   1024
#define IN_DIM  1024
#define OUT_DIM 40960
#define FANIN   7

// Tiling
#define BTILE      32
#define XS_STRIDE  1025           // floats; 1025 % 32 == 1 -> conflict-free gather
#define THREADS    1024
#define WARPS      32
#define GRID_B     (BATCH / BTILE)            // 32
#define GRID_O     40
#define O_BLOCK    (OUT_DIM / GRID_O)         // 1024
#define CHUNK_O    512                        // per meta-buffer chunk
#define O_PER_WARP 16                         // one 16-o tile per warp per chunk

#define XS_FLOATS    (BTILE * XS_STRIDE)      // 32800
#define META_U4      (CHUNK_O * 3)            // 1536 uint4 = 24576 B
#define META_FLOATS  (META_U4 * 4)            // 6144
#define META_WARP_U4 (O_PER_WARP * 3)         // 48 uint4 = 768 B per warp slice
#define PAIR_STG_FLOATS (32 * 33)             // 1056 floats per warp PAIR
#define NPAIRS       (WARPS / 2)              // 16
#define SMEM_FLOATS  (XS_FLOATS + META_FLOATS + NPAIRS * PAIR_STG_FLOATS)
#define SMEM_BYTES   (SMEM_FLOATS * 4)        // 131200+24576+67584 = 223360 B

#define FILL_ITERS   (BTILE * (IN_DIM / 4) / THREADS)   // 8

// Pair-scoped named barrier: only the two warps of a pair exchange staging
// data, so sync at 64-thread scope (16 HW barriers = 16 pairs). The single
// fill-time __syncthreads fully drains barrier 0 before named reuse.
#define PAIR_BAR(pid) \
    asm volatile("bar.sync %0, 64;" :: "r"(pid) : "memory")

// Packed per-output metadata: 48B = uint4 (7x u16 idx*4) + 7 f32 vals + pad
__device__ __align__(16) uint4 g_meta[OUT_DIM * 3];

__global__ void prep_kernel(const int* __restrict__ idx,
                            const float* __restrict__ vals) {
    int o = blockIdx.x * blockDim.x + threadIdx.x;
    if (o >= OUT_DIM) return;
    unsigned id[FANIN];
    float v[FANIN];
#pragma unroll
    for (int k = 0; k < FANIN; k++) {
        id[k] = (unsigned)idx[o * FANIN + k] * 4u;   // pre-scale to byte offset
        v[k]  = vals[o * FANIN + k];
    }
    uint4 mi, ma, mb;
    mi.x = id[0] | (id[1] << 16);
    mi.y = id[2] | (id[3] << 16);
    mi.z = id[4] | (id[5] << 16);
    mi.w = id[6];
    ma.x = __float_as_uint(v[0]); ma.y = __float_as_uint(v[1]);
    ma.z = __float_as_uint(v[2]); ma.w = __float_as_uint(v[3]);
    mb.x = __float_as_uint(v[4]); mb.y = __float_as_uint(v[5]);
    mb.z = __float_as_uint(v[6]); mb.w = 0u;
    uint4* dst = g_meta + (size_t)o * 3;
    dst[0] = mi; dst[1] = ma; dst[2] = mb;
}

// Dot product of 7 gathered x values with 7 vals. xb is this lane's smem row
// base (byte pointer). Gathers are conflict-free: bank = (lane + idx) % 32.
__device__ __forceinline__ float dot7(const char* xb, uint4 mi, uint4 ma, uint4 mb) {
    float g0 = *reinterpret_cast<const float*>(xb + (mi.x & 0xFFFFu));
    float g1 = *reinterpret_cast<const float*>(xb + (mi.x >> 16));
    float g2 = *reinterpret_cast<const float*>(xb + (mi.y & 0xFFFFu));
    float g3 = *reinterpret_cast<const float*>(xb + (mi.y >> 16));
    float g4 = *reinterpret_cast<const float*>(xb + (mi.z & 0xFFFFu));
    float g5 = *reinterpret_cast<const float*>(xb + (mi.z >> 16));
    float g6 = *reinterpret_cast<const float*>(xb + (mi.w & 0xFFFFu));
    float s0 = fmaf(__uint_as_float(ma.x), g0, __uint_as_float(ma.y) * g1);
    float s1 = fmaf(__uint_as_float(ma.z), g2, __uint_as_float(ma.w) * g3);
    float s2 = fmaf(__uint_as_float(mb.x), g4, __uint_as_float(mb.y) * g5);
    float s3 = __uint_as_float(mb.z) * g6;
    return (s0 + s1) + (s2 + s3);
}

// CTA-wide meta chunk load (only used for chunk 0, overlapped with fill).
__device__ __forceinline__ void load_meta_chunk(uint4* meta_s, int o_chunk) {
    const char* gsrc = reinterpret_cast<const char*>(g_meta + (size_t)o_chunk * 3);
    unsigned sbase = (unsigned)__cvta_generic_to_shared(meta_s);
    for (int i = threadIdx.x; i < META_U4; i += THREADS) {
        unsigned sdst = sbase + i * 16;
        asm volatile("cp.async.cg.shared.global [%0], [%1], 16;\n"
                     :: "r"(sdst), "l"(gsrc + (size_t)i * 16));
    }
    asm volatile("cp.async.commit_group;\n");
}

// Warp-local meta slice reload (chunk 1): each warp refreshes ONLY its own
// 48-uint4 slice — no cross-warp hazard, so no CTA barrier needed at all.
__device__ __forceinline__ void load_meta_warp(uint4* dst, const uint4* gsrc,
                                               int lane) {
    unsigned sbase = (unsigned)__cvta_generic_to_shared(dst);
    asm volatile("cp.async.cg.shared.global [%0], [%1], 16;\n"
                 :: "r"(sbase + lane * 16), "l"(gsrc + lane));
    if (lane < META_WARP_U4 - 32) {
        asm volatile("cp.async.cg.shared.global [%0], [%1], 16;\n"
                     :: "r"(sbase + (32 + lane) * 16), "l"(gsrc + 32 + lane));
    }
    asm volatile("cp.async.commit_group;\n");
}

extern __shared__ float smem_all[];
// layout: [XS_FLOATS] x-tile | [META_FLOATS] meta chunk | [NPAIRS][1056] staging

__global__ __launch_bounds__(THREADS, 1)
void mb_proj_kernel(const float* __restrict__ x, float* __restrict__ y) {
    float* xs = smem_all;
    uint4* meta_s = reinterpret_cast<uint4*>(smem_all + XS_FLOATS);
    const int b0    = blockIdx.y * BTILE;
    const int o_cta = blockIdx.x * O_BLOCK;

    // ---- Async meta load for chunk 0 (overlaps x-tile fill) --------------
    load_meta_chunk(meta_s, o_cta);

    // ---- Fill smem x tile: 32 rows x 1024 floats, stride 1025 -------------
    // Row stride 4100B is only 4B-aligned -> cp.async.16 illegal here; use
    // batched LDG.128 into registers (MLP=8) + scalar STS (proven R8).
    // STS banks = (r + 4c + j) mod 32 cover all 32 -> conflict-free.
    {
        const float4* xg = reinterpret_cast<const float4*>(x + (size_t)b0 * IN_DIM);
        float4 v[FILL_ITERS];
#pragma unroll
        for (int i = 0; i < FILL_ITERS; i++) {
            int t = threadIdx.x + i * THREADS;
            int lane5 = t & 31;
            int blk   = t >> 5;
            int r = ((blk >> 5) << 2) + (lane5 >> 3);   // 0..31
            int c = ((blk & 31) << 3) + (lane5 & 7);    // 0..255 (float4 units)
            v[i] = xg[r * (IN_DIM / 4) + c];
        }
#pragma unroll
        for (int i = 0; i < FILL_ITERS; i++) {
            int t = threadIdx.x + i * THREADS;
            int lane5 = t & 31;
            int blk   = t >> 5;
            int r = ((blk >> 5) << 2) + (lane5 >> 3);
            int c = ((blk & 31) << 3) + (lane5 & 7);
            float* d = xs + r * XS_STRIDE + (c << 2);
            d[0] = v[i].x; d[1] = v[i].y; d[2] = v[i].z; d[3] = v[i].w;
        }
    }
    asm volatile("cp.async.wait_group 0;\n");
    __syncthreads();   // ONLY full-CTA barrier in the kernel

    const int warp = threadIdx.x >> 5;
    const int lane = threadIdx.x & 31;
    const int pair = warp >> 1;
    const int w2   = warp & 1;

    // Compute mapping: lane = batch row, o uniform across warp.
    const char* xb = reinterpret_cast<const char*>(xs) + lane * (XS_STRIDE * 4);
    // Warp-PAIR staging: 32 o x 32 b (stride 33, conflict-free both phases)
    float* stgp  = smem_all + XS_FLOATS + META_FLOATS + pair * PAIR_STG_FLOATS;
    float* stg_w = stgp + w2 * (16 * 33);          // this warp's 16-o half
    uint4* mp    = meta_s + warp * META_WARP_U4;   // this warp's meta slice

#pragma unroll
    for (int chunk = 0; chunk < 2; chunk++) {
        // ---- Compute 16 outputs into pair staging; meta via bcast LDS ----
        // Explicit next-meta rotation keeps the LDS pipeline ahead of the
        // staging STS (ptxas must assume smem aliasing otherwise).
        {
            uint4 c0 = mp[0], c1 = mp[1], c2 = mp[2];
#pragma unroll
            for (int s = 0; s < 16; s++) {
                uint4 n0, n1, n2;
                if (s < 15) {
                    const uint4* np = mp + 3 * (s + 1);
                    n0 = np[0]; n1 = np[1]; n2 = np[2];
                } else {
                    n0 = c0; n1 = c1; n2 = c2;
                }
                // STS bank = (s + lane) % 32 -> conflict-free
                stg_w[s * 33 + lane] = dot7(xb, c0, c1, c2);
                c0 = n0; c1 = n1; c2 = n2;
            }
        }

        if (chunk == 0) {
            // This warp finished reading its chunk-0 meta slice -> refresh
            // it (warp-local, no other warp touches it). Latency hides
            // under the store phase; waited on after the stores.
            load_meta_warp(mp,
                           g_meta + (size_t)(o_cta + CHUNK_O + warp * O_PER_WARP) * 3,
                           lane);
        }

        PAIR_BAR(pair);   // partner's staging half visible

        // ---- Store pair tile: 32 o x 32 b, coalesced 128B rows ----------
        // lane = o. LDS bank = (lane*33 + b) % 32 = (lane + b) % 32, all 32
        // distinct -> conflict-free. Each STG covers one contiguous 128B
        // row segment -> 1 wavefront per instruction.
        {
            const int o_pair = o_cta + chunk * CHUNK_O + pair * 32;
            float* yp = y + (size_t)(b0 + 16 * w2) * OUT_DIM + o_pair + lane;
#pragma unroll
            for (int i = 0; i < 16; i++) {
                yp[(size_t)i * OUT_DIM] = stgp[lane * 33 + 16 * w2 + i];
            }
        }

        if (chunk == 0) {
            PAIR_BAR(pair);   // pair done reading staging -> safe to reuse
            asm volatile("cp.async.wait_group 0;\n");   // my meta slice ready
        }
    }
}

extern "C" void kernel_launch(void* const* d_in, const int* in_sizes, int n_in,
                              void* d_out, int out_size) {
    const float* x    = (const float*)d_in[0];   // [1024, 1024] f32
    const float* vals = (const float*)d_in[1];   // [40960, 7]   f32
    const int*   idx  = (const int*)d_in[2];     // [40960, 7]   i32
    float*       y    = (float*)d_out;           // [1024, 40960] f32

    (void)in_sizes; (void)n_in; (void)out_size;

    cudaFuncSetAttribute(mb_proj_kernel,
                         cudaFuncAttributeMaxDynamicSharedMemorySize, SMEM_BYTES);

    prep_kernel<<<(OUT_DIM + 255) / 256, 256>>>(idx, vals);

    dim3 grid(GRID_O, GRID_B);
    mb_proj_kernel<<<grid, THREADS, SMEM_BYTES>>>(x, y);
}

// round 13
// speedup vs baseline: 1.8460x; 1.1810x over previous
#include <cuda_runtime.h>
#include <stdint.h>

// Problem constants (fixed by the dataset)
#define BATCH   1024
#define IN_DIM  1024
#define OUT_DIM 40960
#define FANIN   7

// Tiling
#define BTILE      32
#define XS_STRIDE  1025           // floats; 1025 % 32 == 1 -> conflict-free gather
#define THREADS    1024
#define WARPS      32
#define CHUNK_O    512            // o per work item (one 16-o tile per warp)
#define O_PER_WARP 16
#define OBLK       (OUT_DIM / CHUNK_O)        // 80 o-blocks
#define NB         (BATCH / BTILE)            // 32 b-tiles
#define N_ITEMS    (NB * OBLK)                // 2560 work items
#define N_CTA      148                        // persistent, 1 CTA/SM

#define XS_FLOATS    (BTILE * XS_STRIDE)      // 32800
#define META_U4      (CHUNK_O * 3)            // 1536 uint4 = 24576 B
#define META_FLOATS  (META_U4 * 4)            // 6144
#define META_WARP_U4 (O_PER_WARP * 3)         // 48 uint4 = 768 B per warp slice
#define PAIR_STG_FLOATS (32 * 33)             // 1056 floats per warp PAIR
#define NPAIRS       (WARPS / 2)              // 16
#define SMEM_FLOATS  (XS_FLOATS + META_FLOATS + NPAIRS * PAIR_STG_FLOATS)
#define SMEM_BYTES   (SMEM_FLOATS * 4)        // 223360 B

#define FILL_ITERS   (BTILE * (IN_DIM / 4) / THREADS)   // 8

// Quad-scoped named barrier (4 warps = 128 threads). HW barriers 1..8 only;
// barrier 0 is reserved exclusively for __syncthreads (refills) — mixing
// different arrival counts on one barrier ID is UB, so they must not share.
#define QUAD_BAR(q) \
    asm volatile("bar.sync %0, 128;" :: "r"((q) + 1) : "memory")

// Packed per-output metadata: 48B = uint4 (7x u16 idx*4) + 7 f32 vals + pad
__device__ __align__(16) uint4 g_meta[OUT_DIM * 3];

__global__ void prep_kernel(const int* __restrict__ idx,
                            const float* __restrict__ vals) {
    int o = blockIdx.x * blockDim.x + threadIdx.x;
    if (o >= OUT_DIM) return;
    unsigned id[FANIN];
    float v[FANIN];
#pragma unroll
    for (int k = 0; k < FANIN; k++) {
        id[k] = (unsigned)idx[o * FANIN + k] * 4u;   // pre-scale to byte offset
        v[k]  = vals[o * FANIN + k];
    }
    uint4 mi, ma, mb;
    mi.x = id[0] | (id[1] << 16);
    mi.y = id[2] | (id[3] << 16);
    mi.z = id[4] | (id[5] << 16);
    mi.w = id[6];
    ma.x = __float_as_uint(v[0]); ma.y = __float_as_uint(v[1]);
    ma.z = __float_as_uint(v[2]); ma.w = __float_as_uint(v[3]);
    mb.x = __float_as_uint(v[4]); mb.y = __float_as_uint(v[5]);
    mb.z = __float_as_uint(v[6]); mb.w = 0u;
    uint4* dst = g_meta + (size_t)o * 3;
    dst[0] = mi; dst[1] = ma; dst[2] = mb;
}

// Dot product of 7 gathered x values with 7 vals. xb is this lane's smem row
// base (byte pointer). Gathers are conflict-free: bank = (lane + idx) % 32.
__device__ __forceinline__ float dot7(const char* xb, uint4 mi, uint4 ma, uint4 mb) {
    float g0 = *reinterpret_cast<const float*>(xb + (mi.x & 0xFFFFu));
    float g1 = *reinterpret_cast<const float*>(xb + (mi.x >> 16));
    float g2 = *reinterpret_cast<const float*>(xb + (mi.y & 0xFFFFu));
    float g3 = *reinterpret_cast<const float*>(xb + (mi.y >> 16));
    float g4 = *reinterpret_cast<const float*>(xb + (mi.z & 0xFFFFu));
    float g5 = *reinterpret_cast<const float*>(xb + (mi.z >> 16));
    float g6 = *reinterpret_cast<const float*>(xb + (mi.w & 0xFFFFu));
    float s0 = fmaf(__uint_as_float(ma.x), g0, __uint_as_float(ma.y) * g1);
    float s1 = fmaf(__uint_as_float(ma.z), g2, __uint_as_float(ma.w) * g3);
    float s2 = fmaf(__uint_as_float(mb.x), g4, __uint_as_float(mb.y) * g5);
    float s3 = __uint_as_float(mb.z) * g6;
    return (s0 + s1) + (s2 + s3);
}

// CTA-wide meta chunk load (first item only, overlapped with first fill).
__device__ __forceinline__ void load_meta_chunk(uint4* meta_s, int o_chunk) {
    const char* gsrc = reinterpret_cast<const char*>(g_meta + (size_t)o_chunk * 3);
    unsigned sbase = (unsigned)__cvta_generic_to_shared(meta_s);
    for (int i = threadIdx.x; i < META_U4; i += THREADS) {
        unsigned sdst = sbase + i * 16;
        asm volatile("cp.async.cg.shared.global [%0], [%1], 16;\n"
                     :: "r"(sdst), "l"(gsrc + (size_t)i * 16));
    }
    asm volatile("cp.async.commit_group;\n");
}

// Warp-local meta slice prefetch: each warp refreshes ONLY its own 48-uint4
// slice — no cross-warp hazard, so no CTA barrier needed.
__device__ __forceinline__ void load_meta_warp(uint4* dst, const uint4* gsrc,
                                               int lane) {
    unsigned sbase = (unsigned)__cvta_generic_to_shared(dst);
    asm volatile("cp.async.cg.shared.global [%0], [%1], 16;\n"
                 :: "r"(sbase + lane * 16), "l"(gsrc + lane));
    if (lane < META_WARP_U4 - 32) {
        asm volatile("cp.async.cg.shared.global [%0], [%1], 16;\n"
                     :: "r"(sbase + (32 + lane) * 16), "l"(gsrc + 32 + lane));
    }
    asm volatile("cp.async.commit_group;\n");
}

// Fill smem x tile: 32 rows x 1024 floats, stride 1025.
// Row stride 4100B is only 4B-aligned -> cp.async.16 illegal here; batched
// LDG.128 into registers (MLP=8) + scalar STS (proven R8).
// STS banks = (r + 4c + j) mod 32 cover all 32 -> conflict-free.
__device__ __forceinline__ void fill_x(const float* __restrict__ x,
                                       float* xs, int b0) {
    const float4* xg = reinterpret_cast<const float4*>(x + (size_t)b0 * IN_DIM);
    float4 v[FILL_ITERS];
#pragma unroll
    for (int i = 0; i < FILL_ITERS; i++) {
        int t = threadIdx.x + i * THREADS;
        int lane5 = t & 31;
        int blk   = t >> 5;
        int r = ((blk >> 5) << 2) + (lane5 >> 3);   // 0..31
        int c = ((blk & 31) << 3) + (lane5 & 7);    // 0..255 (float4 units)
        v[i] = xg[r * (IN_DIM / 4) + c];
    }
#pragma unroll
    for (int i = 0; i < FILL_ITERS; i++) {
        int t = threadIdx.x + i * THREADS;
        int lane5 = t & 31;
        int blk   = t >> 5;
        int r = ((blk >> 5) << 2) + (lane5 >> 3);
        int c = ((blk & 31) << 3) + (lane5 & 7);
        float* d = xs + r * XS_STRIDE + (c << 2);
        d[0] = v[i].x; d[1] = v[i].y; d[2] = v[i].z; d[3] = v[i].w;
    }
}

extern __shared__ float smem_all[];
// layout: [XS_FLOATS] x-tile | [META_FLOATS] meta chunk | [NPAIRS][1056] staging

__global__ __launch_bounds__(THREADS, 1)
void mb_proj_kernel(const float* __restrict__ x, float* __restrict__ y) {
    float* xs = smem_all;
    uint4* meta_s = reinterpret_cast<uint4*>(smem_all + XS_FLOATS);

    // Persistent static partition: contiguous item range, b-major ordering
    // (item = b_idx*80 + oblk) -> each CTA crosses <= 1 b-boundary ->
    // <= 2 x-tile fills per CTA (was 1 fill per o-block CTA before).
    const int istart = (int)((long)blockIdx.x * N_ITEMS / N_CTA);
    const int iend   = (int)((long)(blockIdx.x + 1) * N_ITEMS / N_CTA);

    // First item's meta (CTA-wide), overlapped with first x fill.
    load_meta_chunk(meta_s, (istart % OBLK) * CHUNK_O);

    int cur_b = istart / OBLK;
    fill_x(x, xs, cur_b * BTILE);
    asm volatile("cp.async.wait_group 0;\n");
    __syncthreads();

    const int warp = threadIdx.x >> 5;
    const int lane = threadIdx.x & 31;
    const int pair = warp >> 1;
    const int w2   = warp & 1;
    const int quad = warp >> 2;

    // Compute mapping: lane = batch row, o uniform across warp.
    const char* xb = reinterpret_cast<const char*>(xs) + lane * (XS_STRIDE * 4);
    // Warp-PAIR staging: 32 o x 32 b (stride 33, conflict-free both phases)
    float* stgp  = smem_all + XS_FLOATS + META_FLOATS + pair * PAIR_STG_FLOATS;
    float* stg_w = stgp + w2 * (16 * 33);          // this warp's 16-o half
    uint4* mp    = meta_s + warp * META_WARP_U4;   // this warp's meta slice

    for (int item = istart; item < iend; item++) {
        const int b_idx = item / OBLK;
        const int oblk  = item - b_idx * OBLK;

        // Refill x tile on b-boundary (CTA-uniform branch; <=1 per CTA).
        if (b_idx != cur_b) {
            __syncthreads();                 // all warps past previous stores
            fill_x(x, xs, b_idx * BTILE);
            cur_b = b_idx;
            __syncthreads();
        }

        // ---- Compute 16 outputs into pair staging; meta via bcast LDS ----
        // Explicit next-meta rotation keeps the LDS pipeline ahead of the
        // staging STS (ptxas must assume smem aliasing otherwise).
        {
            uint4 c0 = mp[0], c1 = mp[1], c2 = mp[2];
#pragma unroll
            for (int s = 0; s < 16; s++) {
                uint4 n0, n1, n2;
                if (s < 15) {
                    const uint4* np = mp + 3 * (s + 1);
                    n0 = np[0]; n1 = np[1]; n2 = np[2];
                } else {
                    n0 = c0; n1 = c1; n2 = c2;
                }
                // STS bank = (s + lane) % 32 -> conflict-free
                stg_w[s * 33 + lane] = dot7(xb, c0, c1, c2);
                c0 = n0; c1 = n1; c2 = n2;
            }
        }

        // Prefetch next item's meta slice (warp-local); latency hides under
        // the store phase below.
        if (item + 1 < iend) {
            const int noblk = (item + 1) % OBLK;
            load_meta_warp(mp,
                g_meta + (size_t)(noblk * CHUNK_O + warp * O_PER_WARP) * 3,
                lane);
        }

        QUAD_BAR(quad);   // partner's staging half visible

        // ---- Store pair tile: 32 o x 32 b, coalesced 128B rows ----------
        // lane = o. LDS bank = (lane*33 + b) % 32 = (lane + b) % 32, all 32
        // distinct -> conflict-free. Each STG covers one contiguous 128B
        // row segment -> 1 wavefront per instruction.
        {
            const int o_pair = oblk * CHUNK_O + pair * 32;
            float* yp = y + (size_t)(cur_b * BTILE + 16 * w2) * OUT_DIM
                          + o_pair + lane;
#pragma unroll
            for (int i = 0; i < 16; i++) {
                yp[(size_t)i * OUT_DIM] = stgp[lane * 33 + 16 * w2 + i];
            }
        }

        QUAD_BAR(quad);   // pair done reading staging -> safe to reuse

        if (item + 1 < iend) {
            asm volatile("cp.async.wait_group 0;\n");  // my meta slice ready
            __syncwarp();   // order other lanes' async copies for my reads
        }
    }
}

extern "C" void kernel_launch(void* const* d_in, const int* in_sizes, int n_in,
                              void* d_out, int out_size) {
    const float* x    = (const float*)d_in[0];   // [1024, 1024] f32
    const float* vals = (const float*)d_in[1];   // [40960, 7]   f32
    const int*   idx  = (const int*)d_in[2];     // [40960, 7]   i32
    float*       y    = (float*)d_out;           // [1024, 40960] f32

    (void)in_sizes; (void)n_in; (void)out_size;

    cudaFuncSetAttribute(mb_proj_kernel,
                         cudaFuncAttributeMaxDynamicSharedMemorySize, SMEM_BYTES);

    prep_kernel<<<(OUT_DIM + 255) / 256, 256>>>(idx, vals);

    mb_proj_kernel<<<N_CTA, THREADS, SMEM_BYTES>>>(x, y);
}

// round 15
// speedup vs baseline: 2.1724x; 1.1768x over previous
#include <cuda_runtime.h>
#include <stdint.h>

// Problem constants (fixed by the dataset)
#define BATCH   1024
#define IN_DIM  1024
#define OUT_DIM 40960
#define FANIN   7

// Tiling
#define BTILE      32             // 16 float2-interleaved pair-rows
#define NPAIR_B    16
#define XS2_STRIDE 1025           // float2 units per pair-row; 1025%32==1
#define THREADS    1024
#define WARPS      32
#define CHUNK_O    512            // o per work item (16 o per warp)
#define O_PER_WARP 16
#define OBLK       (OUT_DIM / CHUNK_O)        // 80
#define NB         (BATCH / BTILE)            // 32
#define N_ITEMS    (NB * OBLK)                // 2560
#define N_CTA      148

#define XS_FLOATS    (NPAIR_B * XS2_STRIDE * 2)   // 32800 floats (131200 B)
#define META_U4      (CHUNK_O * 3)                // 1536 uint4 = 24576 B
#define META_FLOATS  (META_U4 * 4)                // 6144
#define META_WARP_U4 (O_PER_WARP * 3)             // 48 uint4 per warp slice
#define STG_STRIDE   35                           // floats per o row in staging
#define PAIR_STG_FLOATS (32 * STG_STRIDE)         // 1120 floats per warp PAIR
#define NPAIRS       (WARPS / 2)                  // 16
#define SMEM_FLOATS  (XS_FLOATS + META_FLOATS + NPAIRS * PAIR_STG_FLOATS)
#define SMEM_BYTES   (SMEM_FLOATS * 4)            // 227456 B (<= 227KB cap)

#define FILL_ITERS   (BTILE * (IN_DIM / 4) / THREADS)   // 8

// Quad-scoped named barrier (4 warps = 128 threads). HW barriers 1..8 only;
// barrier 0 reserved for __syncthreads (refills) — mixed arrival counts on
// one barrier ID are UB.
#define QUAD_BAR(q) \
    asm volatile("bar.sync %0, 128;" :: "r"((q) + 1) : "memory")

// Packed per-output metadata: 48B = uint4 (7x u16 idx*8) + 7 f32 vals + pad
__device__ __align__(16) uint4 g_meta[OUT_DIM * 3];

__global__ void prep_kernel(const int* __restrict__ idx,
                            const float* __restrict__ vals) {
    int o = blockIdx.x * blockDim.x + threadIdx.x;
    if (o >= OUT_DIM) return;
    unsigned id[FANIN];
    float v[FANIN];
#pragma unroll
    for (int k = 0; k < FANIN; k++) {
        id[k] = (unsigned)idx[o * FANIN + k] * 8u;   // float2 byte offset (<=8184)
        v[k]  = vals[o * FANIN + k];
    }
    uint4 mi, ma, mb;
    mi.x = id[0] | (id[1] << 16);
    mi.y = id[2] | (id[3] << 16);
    mi.z = id[4] | (id[5] << 16);
    mi.w = id[6];
    ma.x = __float_as_uint(v[0]); ma.y = __float_as_uint(v[1]);
    ma.z = __float_as_uint(v[2]); ma.w = __float_as_uint(v[3]);
    mb.x = __float_as_uint(v[4]); mb.y = __float_as_uint(v[5]);
    mb.z = __float_as_uint(v[6]); mb.w = 0u;
    uint4* dst = g_meta + (size_t)o * 3;
    dst[0] = mi; dst[1] = ma; dst[2] = mb;
}

// Dual-row dot product: xb2 is this lane's pair-row base (byte pointer into
// float2-interleaved x tile). Each gather is an LDS.64 fetching BOTH batch
// rows of the pair; conflict-free for any idx (2 words/bank exactly).
__device__ __forceinline__ float2 dot7x2(const char* xb2, uint4 mi, uint4 ma,
                                         uint4 mb) {
    float2 g0 = *reinterpret_cast<const float2*>(xb2 + (mi.x & 0xFFFFu));
    float2 g1 = *reinterpret_cast<const float2*>(xb2 + (mi.x >> 16));
    float2 g2 = *reinterpret_cast<const float2*>(xb2 + (mi.y & 0xFFFFu));
    float2 g3 = *reinterpret_cast<const float2*>(xb2 + (mi.y >> 16));
    float2 g4 = *reinterpret_cast<const float2*>(xb2 + (mi.z & 0xFFFFu));
    float2 g5 = *reinterpret_cast<const float2*>(xb2 + (mi.z >> 16));
    float2 g6 = *reinterpret_cast<const float2*>(xb2 + (mi.w & 0xFFFFu));
    float v0 = __uint_as_float(ma.x), v1 = __uint_as_float(ma.y);
    float v2 = __uint_as_float(ma.z), v3 = __uint_as_float(ma.w);
    float v4 = __uint_as_float(mb.x), v5 = __uint_as_float(mb.y);
    float v6 = __uint_as_float(mb.z);
    float2 r;
    {
        float s0 = fmaf(v0, g0.x, v1 * g1.x);
        float s1 = fmaf(v2, g2.x, v3 * g3.x);
        float s2 = fmaf(v4, g4.x, v5 * g5.x);
        float s3 = v6 * g6.x;
        r.x = (s0 + s1) + (s2 + s3);
    }
    {
        float s0 = fmaf(v0, g0.y, v1 * g1.y);
        float s1 = fmaf(v2, g2.y, v3 * g3.y);
        float s2 = fmaf(v4, g4.y, v5 * g5.y);
        float s3 = v6 * g6.y;
        r.y = (s0 + s1) + (s2 + s3);
    }
    return r;
}

// CTA-wide meta chunk load (first item only, overlapped with first fill).
__device__ __forceinline__ void load_meta_chunk(uint4* meta_s, int o_chunk) {
    const char* gsrc = reinterpret_cast<const char*>(g_meta + (size_t)o_chunk * 3);
    unsigned sbase = (unsigned)__cvta_generic_to_shared(meta_s);
    for (int i = threadIdx.x; i < META_U4; i += THREADS) {
        unsigned sdst = sbase + i * 16;
        asm volatile("cp.async.cg.shared.global [%0], [%1], 16;\n"
                     :: "r"(sdst), "l"(gsrc + (size_t)i * 16));
    }
    asm volatile("cp.async.commit_group;\n");
}

// Warp-local meta slice prefetch (48 uint4, no cross-warp hazard).
__device__ __forceinline__ void load_meta_warp(uint4* dst, const uint4* gsrc,
                                               int lane) {
    unsigned sbase = (unsigned)__cvta_generic_to_shared(dst);
    asm volatile("cp.async.cg.shared.global [%0], [%1], 16;\n"
                 :: "r"(sbase + lane * 16), "l"(gsrc + lane));
    if (lane < META_WARP_U4 - 32) {
        asm volatile("cp.async.cg.shared.global [%0], [%1], 16;\n"
                     :: "r"(sbase + (32 + lane) * 16), "l"(gsrc + 32 + lane));
    }
    asm volatile("cp.async.commit_group;\n");
}

// Fill smem x tile, float2-interleaved: xs[p][i] = (x[2p][i], x[2p+1][i]),
// pair-row stride 2050 floats. Batched LDG.128 (MLP=8) then scalar STS.
// STS bank = (2p + 8c + 2j + e) mod 32; over a warp (a,b,c5 decomposition)
// = 4R + {0..3} + 8*c5 -> all 32 banks distinct per j -> conflict-free.
__device__ __forceinline__ void fill_x(const float* __restrict__ x,
                                       float* xs, int b0) {
    const float4* xg = reinterpret_cast<const float4*>(x + (size_t)b0 * IN_DIM);
    float4 v[FILL_ITERS];
#pragma unroll
    for (int i = 0; i < FILL_ITERS; i++) {
        int t = threadIdx.x + i * THREADS;
        int lane5 = t & 31;
        int blk   = t >> 5;
        int r = ((blk >> 5) << 2) + (lane5 >> 3);   // 0..31
        int c = ((blk & 31) << 3) + (lane5 & 7);    // 0..255 (float4 units)
        v[i] = xg[r * (IN_DIM / 4) + c];
    }
#pragma unroll
    for (int i = 0; i < FILL_ITERS; i++) {
        int t = threadIdx.x + i * THREADS;
        int lane5 = t & 31;
        int blk   = t >> 5;
        int r = ((blk >> 5) << 2) + (lane5 >> 3);
        int c = ((blk & 31) << 3) + (lane5 & 7);
        int p = r >> 1, e = r & 1;
        float* d = xs + p * (XS2_STRIDE * 2) + (c << 3) + e;
        d[0] = v[i].x; d[2] = v[i].y; d[4] = v[i].z; d[6] = v[i].w;
    }
}

extern __shared__ float smem_all[];
// layout: [32800] x-tile (interleaved) | [6144] meta | [16][1120] staging

__global__ __launch_bounds__(THREADS, 1)
void mb_proj_kernel(const float* __restrict__ x, float* __restrict__ y) {
    float* xs = smem_all;
    uint4* meta_s = reinterpret_cast<uint4*>(smem_all + XS_FLOATS);

    // Persistent static partition, b-major item order (item = b*80 + oblk)
    // -> <=1 b-boundary crossing -> <=2 x fills per CTA.
    const int istart = (int)((long)blockIdx.x * N_ITEMS / N_CTA);
    const int iend   = (int)((long)(blockIdx.x + 1) * N_ITEMS / N_CTA);

    load_meta_chunk(meta_s, (istart % OBLK) * CHUNK_O);

    int cur_b = istart / OBLK;
    fill_x(x, xs, cur_b * BTILE);
    asm volatile("cp.async.wait_group 0;\n");
    __syncthreads();

    const int warp = threadIdx.x >> 5;
    const int lane = threadIdx.x & 31;
    const int pair = warp >> 1;
    const int w2   = warp & 1;
    const int quad = warp >> 2;
    const int p    = lane & 15;    // batch pair-row
    const int os   = lane >> 4;    // o sub-index within the 2-o iteration

    // Gather base: this lane's pair-row (8200 B per pair-row).
    const char* xb2 = reinterpret_cast<const char*>(xs)
                    + p * (XS2_STRIDE * 2 * 4);
    float* stgp = smem_all + XS_FLOATS + META_FLOATS + pair * PAIR_STG_FLOATS;
    uint4* mp   = meta_s + warp * META_WARP_U4;   // this warp's meta slice

    for (int item = istart; item < iend; item++) {
        const int b_idx = item / OBLK;
        const int oblk  = item - b_idx * OBLK;

        // Refill x tile on b-boundary (CTA-uniform branch; <=1 per CTA).
        if (b_idx != cur_b) {
            __syncthreads();
            fill_x(x, xs, b_idx * BTILE);
            cur_b = b_idx;
            __syncthreads();
        }

        // ---- Compute: 8 iterations x 2 o x 32 b -------------------------
        // Meta LDS.128 serves two 16B records (48B apart -> disjoint bank
        // quads -> 1 wf). Explicit rotation keeps LDS ahead of staging STS.
        {
            uint4 c0 = mp[os * 3], c1 = mp[os * 3 + 1], c2 = mp[os * 3 + 2];
#pragma unroll
            for (int s = 0; s < 8; s++) {
                uint4 n0, n1, n2;
                if (s < 7) {
                    const uint4* np = mp + (2 * (s + 1) + os) * 3;
                    n0 = np[0]; n1 = np[1]; n2 = np[2];
                } else {
                    n0 = c0; n1 = c1; n2 = c2;
                }
                float2 r = dot7x2(xb2, c0, c1, c2);
                // Staging STS (scalar x2): banks (3*o_loc + 2p + {0,1}),
                // parity split between halves -> conflict-free.
                const int o_loc = 16 * w2 + 2 * s + os;
                stgp[o_loc * STG_STRIDE + 2 * p]     = r.x;
                stgp[o_loc * STG_STRIDE + 2 * p + 1] = r.y;
                c0 = n0; c1 = n1; c2 = n2;
            }
        }

        // Prefetch next item's meta slice (warp-local); hides under stores.
        if (item + 1 < iend) {
            const int noblk = (item + 1) % OBLK;
            load_meta_warp(mp,
                g_meta + (size_t)(noblk * CHUNK_O + warp * O_PER_WARP) * 3,
                lane);
        }

        QUAD_BAR(quad);   // partner's staging half visible

        // ---- Store pair tile: 32 o x 32 b, coalesced 128B rows ----------
        // lane = o'. LDS bank = (3*lane + b) mod 32, gcd(3,32)=1 -> all
        // distinct -> conflict-free. STG: one contiguous 128B row segment.
        {
            const int o_pair = oblk * CHUNK_O + pair * 32;
            const float* sp = stgp + lane * STG_STRIDE + 16 * w2;
            float* yp = y + (size_t)(cur_b * BTILE + 16 * w2) * OUT_DIM
                          + o_pair + lane;
#pragma unroll
            for (int i = 0; i < 16; i++) {
                yp[(size_t)i * OUT_DIM] = sp[i];
            }
        }

        QUAD_BAR(quad);   // pair done reading staging -> safe to reuse

        if (item + 1 < iend) {
            asm volatile("cp.async.wait_group 0;\n");  // my meta slice ready
            __syncwarp();   // order other lanes' async copies for my reads
        }
    }
}

extern "C" void kernel_launch(void* const* d_in, const int* in_sizes, int n_in,
                              void* d_out, int out_size) {
    const float* x    = (const float*)d_in[0];   // [1024, 1024] f32
    const float* vals = (const float*)d_in[1];   // [40960, 7]   f32
    const int*   idx  = (const int*)d_in[2];     // [40960, 7]   i32
    float*       y    = (float*)d_out;           // [1024, 40960] f32

    (void)in_sizes; (void)n_in; (void)out_size;

    cudaFuncSetAttribute(mb_proj_kernel,
                         cudaFuncAttributeMaxDynamicSharedMemorySize, SMEM_BYTES);

    prep_kernel<<<(OUT_DIM + 255) / 256, 256>>>(idx, vals);

    mb_proj_kernel<<<N_CTA, THREADS, SMEM_BYTES>>>(x, y);
}

// round 16
// speedup vs baseline: 2.4807x; 1.1419x over previous
#include <cuda_runtime.h>
#include <cuda_fp16.h>
#include <stdint.h>

// Problem constants (fixed by the dataset)
#define BATCH   1024
#define IN_DIM  1024
#define OUT_DIM 40960
#define FANIN   7

// Tiling
#define BTILE      64             // 32 half2-interleaved pair-rows
#define NPAIR      32
#define XS2_STRIDE 1025           // half2 units per pair-row; 1025%32==1
#define THREADS    1024
#define WARPS      32
#define CHUNK_O    256            // o per work item (8 o per warp)
#define O_PER_WARP 8
#define OBLK       (OUT_DIM / CHUNK_O)        // 160
#define NB         (BATCH / BTILE)            // 16
#define N_ITEMS    (NB * OBLK)                // 2560
#define N_CTA      148

#define XS_SLOTS     (NPAIR * XS2_STRIDE)     // 32800 half2 = 131200 B
#define META_U4      (CHUNK_O * 3)            // 768 uint4 = 12288 B
#define META_FLOATS  (META_U4 * 4)            // 3072 float slots
#define META_WARP_U4 (O_PER_WARP * 3)         // 24 uint4 per warp slice
#define STG2_STRIDE  33                       // float2 per o row (32 + pad)
#define QUAD_STG_F2  (32 * STG2_STRIDE)       // 1056 float2 per quad
#define NQUADS       (WARPS / 4)              // 8
#define SMEM_FLOATS  (XS_SLOTS + META_FLOATS + NQUADS * QUAD_STG_F2 * 2)
#define SMEM_BYTES   (SMEM_FLOATS * 4)        // 211072 B

// Quad-scoped named barrier (4 warps = 128 threads). HW barriers 1..8 only;
// barrier 0 reserved for __syncthreads (refills) — mixed arrival counts on
// one barrier ID are UB.
#define QUAD_BAR(q) \
    asm volatile("bar.sync %0, 128;" :: "r"((q) + 1) : "memory")

// Packed per-output metadata: 48B = uint4 (7x u16 idx*4 = half2 byte offset)
// + 7 f32 vals + pad. vals stay fp32 (only gathered x is fp16).
__device__ __align__(16) uint4 g_meta[OUT_DIM * 3];

__global__ void prep_kernel(const int* __restrict__ idx,
                            const float* __restrict__ vals) {
    int o = blockIdx.x * blockDim.x + threadIdx.x;
    if (o >= OUT_DIM) return;
    unsigned id[FANIN];
    float v[FANIN];
#pragma unroll
    for (int k = 0; k < FANIN; k++) {
        id[k] = (unsigned)idx[o * FANIN + k] * 4u;   // half2 byte offset <=4092
        v[k]  = vals[o * FANIN + k];
    }
    uint4 mi, ma, mb;
    mi.x = id[0] | (id[1] << 16);
    mi.y = id[2] | (id[3] << 16);
    mi.z = id[4] | (id[5] << 16);
    mi.w = id[6];
    ma.x = __float_as_uint(v[0]); ma.y = __float_as_uint(v[1]);
    ma.z = __float_as_uint(v[2]); ma.w = __float_as_uint(v[3]);
    mb.x = __float_as_uint(v[4]); mb.y = __float_as_uint(v[5]);
    mb.z = __float_as_uint(v[6]); mb.w = 0u;
    uint4* dst = g_meta + (size_t)o * 3;
    dst[0] = mi; dst[1] = ma; dst[2] = mb;
}

// Dual-row dot: xb2 = this lane's pair-row base (byte ptr into half2 tile).
// Each gather is LDS.32 (one half2 = rows 2p,2p+1); bank = p + idx mod 32,
// all 32 lanes distinct -> conflict-free for ANY idx. Accumulate in fp32.
__device__ __forceinline__ float2 dot7x2h(const char* xb2, uint4 mi, uint4 ma,
                                          uint4 mb) {
    float2 g0 = __half22float2(*reinterpret_cast<const __half2*>(xb2 + (mi.x & 0xFFFFu)));
    float2 g1 = __half22float2(*reinterpret_cast<const __half2*>(xb2 + (mi.x >> 16)));
    float2 g2 = __half22float2(*reinterpret_cast<const __half2*>(xb2 + (mi.y & 0xFFFFu)));
    float2 g3 = __half22float2(*reinterpret_cast<const __half2*>(xb2 + (mi.y >> 16)));
    float2 g4 = __half22float2(*reinterpret_cast<const __half2*>(xb2 + (mi.z & 0xFFFFu)));
    float2 g5 = __half22float2(*reinterpret_cast<const __half2*>(xb2 + (mi.z >> 16)));
    float2 g6 = __half22float2(*reinterpret_cast<const __half2*>(xb2 + (mi.w & 0xFFFFu)));
    float v0 = __uint_as_float(ma.x), v1 = __uint_as_float(ma.y);
    float v2 = __uint_as_float(ma.z), v3 = __uint_as_float(ma.w);
    float v4 = __uint_as_float(mb.x), v5 = __uint_as_float(mb.y);
    float v6 = __uint_as_float(mb.z);
    float2 r;
    {
        float s0 = fmaf(v0, g0.x, v1 * g1.x);
        float s1 = fmaf(v2, g2.x, v3 * g3.x);
        float s2 = fmaf(v4, g4.x, v5 * g5.x);
        r.x = (s0 + s1) + (s2 + v6 * g6.x);
    }
    {
        float s0 = fmaf(v0, g0.y, v1 * g1.y);
        float s1 = fmaf(v2, g2.y, v3 * g3.y);
        float s2 = fmaf(v4, g4.y, v5 * g5.y);
        r.y = (s0 + s1) + (s2 + v6 * g6.y);
    }
    return r;
}

// CTA-wide meta chunk load (first item only, overlapped with first fill).
__device__ __forceinline__ void load_meta_chunk(uint4* meta_s, int o_chunk) {
    const char* gsrc = reinterpret_cast<const char*>(g_meta + (size_t)o_chunk * 3);
    unsigned sbase = (unsigned)__cvta_generic_to_shared(meta_s);
    for (int i = threadIdx.x; i < META_U4; i += THREADS) {
        unsigned sdst = sbase + i * 16;
        asm volatile("cp.async.cg.shared.global [%0], [%1], 16;\n"
                     :: "r"(sdst), "l"(gsrc + (size_t)i * 16));
    }
    asm volatile("cp.async.commit_group;\n");
}

// Warp-local meta slice prefetch (24 uint4; lanes 0..23). No cross-warp hazard.
__device__ __forceinline__ void load_meta_warp(uint4* dst, const uint4* gsrc,
                                               int lane) {
    unsigned sbase = (unsigned)__cvta_generic_to_shared(dst);
    if (lane < META_WARP_U4) {
        asm volatile("cp.async.cg.shared.global [%0], [%1], 16;\n"
                     :: "r"(sbase + lane * 16), "l"(gsrc + lane));
    }
    asm volatile("cp.async.commit_group;\n");
}

// Fill half2-interleaved x tile: xs2[p][i] = half2(x[2p][i], x[2p+1][i]).
// Task (p, c4): p = (warp&7)*4 + (lane>>3), c4 = it*32 + (warp>>3)*8 + (lane&7).
// LDG: 8 consecutive lanes read 128B contiguous per row -> coalesced.
// STS.32 banks = (p + 4*c4 + j) mod 32: over warp = l2 + 4*b3 + const -> all
// 32 distinct -> conflict-free.
__device__ __forceinline__ void fill_x(const float* __restrict__ x,
                                       __half2* xs2, int b0) {
    const float4* xg = reinterpret_cast<const float4*>(x + (size_t)b0 * IN_DIM);
    const int lane = threadIdx.x & 31;
    const int warp = threadIdx.x >> 5;
    const int p  = ((warp & 7) << 2) | ((lane >> 3) & 3);
    const int cb = ((warp >> 3) << 3) | (lane & 7);
#pragma unroll
    for (int h = 0; h < 2; h++) {
        float4 va[4], vb[4];
#pragma unroll
        for (int t = 0; t < 4; t++) {
            int c4 = ((h * 4 + t) << 5) | cb;
            va[t] = xg[(2 * p)     * (IN_DIM / 4) + c4];
            vb[t] = xg[(2 * p + 1) * (IN_DIM / 4) + c4];
        }
#pragma unroll
        for (int t = 0; t < 4; t++) {
            int c4 = ((h * 4 + t) << 5) | cb;
            __half2* d = xs2 + p * XS2_STRIDE + 4 * c4;
            d[0] = __floats2half2_rn(va[t].x, vb[t].x);  // low = row 2p
            d[1] = __floats2half2_rn(va[t].y, vb[t].y);
            d[2] = __floats2half2_rn(va[t].z, vb[t].z);
            d[3] = __floats2half2_rn(va[t].w, vb[t].w);
        }
    }
}

extern __shared__ float smem_all[];
// layout: [32800 slots] x-tile half2 | [3072] meta | [8][1056 float2] staging

__global__ __launch_bounds__(THREADS, 1)
void mb_proj_kernel(const float* __restrict__ x, float* __restrict__ y) {
    __half2* xs2  = reinterpret_cast<__half2*>(smem_all);
    uint4* meta_s = reinterpret_cast<uint4*>(smem_all + XS_SLOTS);
    float2* stg_base = reinterpret_cast<float2*>(smem_all + XS_SLOTS + META_FLOATS);

    // Persistent static partition, b-major item order (item = b*160 + oblk)
    // -> <=1 b-boundary crossing -> <=2 x fills per CTA.
    const int istart = (int)((long)blockIdx.x * N_ITEMS / N_CTA);
    const int iend   = (int)((long)(blockIdx.x + 1) * N_ITEMS / N_CTA);

    load_meta_chunk(meta_s, (istart % OBLK) * CHUNK_O);

    int cur_b = istart / OBLK;
    fill_x(x, xs2, cur_b * BTILE);
    asm volatile("cp.async.wait_group 0;\n");
    __syncthreads();

    const int warp = threadIdx.x >> 5;
    const int lane = threadIdx.x & 31;
    const int quad = warp >> 2;
    const int wq   = warp & 3;

    // Gather base: lane = pair-row p (4100 B per pair-row).
    const char* xb2 = reinterpret_cast<const char*>(xs2)
                    + lane * (XS2_STRIDE * 4);
    float2* stgq = stg_base + quad * QUAD_STG_F2;
    uint4*  mp   = meta_s + warp * META_WARP_U4;

    for (int item = istart; item < iend; item++) {
        const int b_idx = item / OBLK;
        const int oblk  = item - b_idx * OBLK;

        // Refill x tile on b-boundary (CTA-uniform branch; <=1 per CTA).
        if (b_idx != cur_b) {
            __syncthreads();
            fill_x(x, xs2, b_idx * BTILE);
            cur_b = b_idx;
            __syncthreads();
        }

        // ---- Compute: 8 o (uniform per warp) x 64 b ---------------------
        // Meta via broadcast LDS.128 (rotation keeps LDS ahead of STS).
        // Staging STS.64 float2 at [o_loc*33 + p]: banks 2p+{0,1} -> exactly
        // 2 words/bank = 2 wf = 256B floor.
        {
            uint4 c0 = mp[0], c1 = mp[1], c2 = mp[2];
#pragma unroll
            for (int s = 0; s < O_PER_WARP; s++) {
                uint4 n0, n1, n2;
                if (s < O_PER_WARP - 1) {
                    const uint4* np = mp + 3 * (s + 1);
                    n0 = np[0]; n1 = np[1]; n2 = np[2];
                } else {
                    n0 = c0; n1 = c1; n2 = c2;
                }
                float2 r = dot7x2h(xb2, c0, c1, c2);
                stgq[(wq * O_PER_WARP + s) * STG2_STRIDE + lane] = r;
                c0 = n0; c1 = n1; c2 = n2;
            }
        }

        // Prefetch next item's meta slice (warp-local); hides under stores.
        if (item + 1 < iend) {
            const int noblk = (item + 1) % OBLK;
            load_meta_warp(mp,
                g_meta + (size_t)(noblk * CHUNK_O + warp * O_PER_WARP) * 3,
                lane);
        }

        QUAD_BAR(quad);   // quad's staging tile complete

        // ---- Store quad tile: 32 o x 64 b -------------------------------
        // lane = o. Warp wq handles pair-rows pp = wq*8 + ip. LDS.64 banks
        // 2*lane+{0,1} -> 2 words/bank = floor. Each STG.32 row = 128B
        // contiguous, 32-o aligned -> 1 wf.
        {
            const int o_quad = oblk * CHUNK_O + quad * 32;
            float* ybase = y + (size_t)(cur_b * BTILE) * OUT_DIM + o_quad + lane;
#pragma unroll
            for (int ip = 0; ip < 8; ip++) {
                const int pp = wq * 8 + ip;
                float2 r2 = stgq[lane * STG2_STRIDE + pp];
                ybase[(size_t)(2 * pp)     * OUT_DIM] = r2.x;
                ybase[(size_t)(2 * pp + 1) * OUT_DIM] = r2.y;
            }
        }

        QUAD_BAR(quad);   // quad done reading staging -> safe to reuse

        if (item + 1 < iend) {
            asm volatile("cp.async.wait_group 0;\n");  // my meta slice ready
            __syncwarp();   // order other lanes' async copies for my reads
        }
    }
}

extern "C" void kernel_launch(void* const* d_in, const int* in_sizes, int n_in,
                              void* d_out, int out_size) {
    const float* x    = (const float*)d_in[0];   // [1024, 1024] f32
    const float* vals = (const float*)d_in[1];   // [40960, 7]   f32
    const int*   idx  = (const int*)d_in[2];     // [40960, 7]   i32
    float*       y    = (float*)d_out;           // [1024, 40960] f32

    (void)in_sizes; (void)n_in; (void)out_size;

    cudaFuncSetAttribute(mb_proj_kernel,
                         cudaFuncAttributeMaxDynamicSharedMemorySize, SMEM_BYTES);

    prep_kernel<<<(OUT_DIM + 255) / 256, 256>>>(idx, vals);

    mb_proj_kernel<<<N_CTA, THREADS, SMEM_BYTES>>>(x, y);
}